// round 1
// baseline (speedup 1.0000x reference)
#include <cuda_runtime.h>

// DeepProbLogAdditionReasoner: per-row conv of two length-10 pdfs -> 19 bins, normalized.
// B = in_sizes[0]/10 rows. Pure HBM-streaming kernel; all global traffic coalesced
// via shared-memory staging (pitch-11 input tiles, stride-19 output tile).

#define TPB 256
#define IN_PITCH 11   // gcd(11,32)=1 -> conflict-free per-row smem reads

__global__ __launch_bounds__(TPB) void dpl_add_kernel(
    const float* __restrict__ p1,
    const float* __restrict__ p2,
    float* __restrict__ out,
    int B)
{
    // Union shared buffer:
    //   phase 1: s1 = sm[0 .. TPB*11), s2 = sm[TPB*11 .. TPB*22)   (inputs, pitch 11)
    //   phase 2: so = sm[0 .. TPB*19)                              (outputs, stride 19)
    __shared__ float sm[TPB * 22];

    const int tid  = threadIdx.x;
    const long long base = (long long)blockIdx.x * TPB;   // first row of this block
    const int rows = (B - base < TPB) ? (int)(B - base) : TPB;

    // ---- Phase 1: coalesced global -> smem (both inputs) ----
    const float* g1 = p1 + base * 10;
    const float* g2 = p2 + base * 10;
    const int nElems = rows * 10;
    #pragma unroll
    for (int i = tid; i < TPB * 10; i += TPB) {
        if (i < nElems) {
            int row = i / 10;
            int col = i - row * 10;
            sm[row * IN_PITCH + col]            = g1[i];
            sm[TPB * IN_PITCH + row * IN_PITCH + col] = g2[i];
        }
    }
    __syncthreads();

    // ---- Per-row convolution in registers ----
    float r[19];
    if (tid < rows) {
        float a[10], b[10];
        #pragma unroll
        for (int i = 0; i < 10; i++) {
            a[i] = sm[tid * IN_PITCH + i];
            b[i] = sm[TPB * IN_PITCH + tid * IN_PITCH + i];
        }
        #pragma unroll
        for (int k = 0; k < 19; k++) r[k] = 0.0f;
        #pragma unroll
        for (int i = 0; i < 10; i++) {
            #pragma unroll
            for (int j = 0; j < 10; j++) {
                r[i + j] = fmaf(a[i], b[j], r[i + j]);
            }
        }
        float s = 0.0f;
        #pragma unroll
        for (int k = 0; k < 19; k++) s += r[k];
        float inv = 1.0f / (s + 1e-9f);
        #pragma unroll
        for (int k = 0; k < 19; k++) r[k] *= inv;
    }

    __syncthreads();   // inputs consumed; smem now reusable for output staging

    // ---- Phase 2: smem staging (stride 19, conflict-free) -> coalesced global ----
    if (tid < rows) {
        #pragma unroll
        for (int k = 0; k < 19; k++) sm[tid * 19 + k] = r[k];
    }
    __syncthreads();

    float* go = out + base * 19;
    const int nOut = rows * 19;
    #pragma unroll
    for (int i = tid; i < TPB * 19; i += TPB) {
        if (i < nOut) go[i] = sm[i];
    }
}

extern "C" void kernel_launch(void* const* d_in, const int* in_sizes, int n_in,
                              void* d_out, int out_size) {
    const float* p1 = (const float*)d_in[0];
    const float* p2 = (const float*)d_in[1];
    float* out = (float*)d_out;
    const int B = in_sizes[0] / 10;
    const int grid = (B + TPB - 1) / TPB;
    dpl_add_kernel<<<grid, TPB>>>(p1, p2, out, B);
}

// round 2
// speedup vs baseline: 1.0693x; 1.0693x over previous
#include <cuda_runtime.h>

// DeepProbLogAdditionReasoner: per-row conv of two length-10 pdfs -> 19 bins, normalized.
// Fully vectorized (float4) streaming kernel with smem staging:
//   phase 1: float4 copy global -> linear smem (pitch 10)
//   phase 2: per-row 10x10 FMA conv + normalize in registers
//   phase 3: stride-19 smem stage -> float4 coalesced global store

#define TPB 256
#define NV4_IN  (TPB * 10 / 4)   // 640 float4 per input array per block
#define NV4_OUT (TPB * 19 / 4)   // 1216 float4 per block

__global__ __launch_bounds__(TPB) void dpl_add_kernel(
    const float* __restrict__ p1,
    const float* __restrict__ p2,
    float* __restrict__ out,
    int B)
{
    // phase 1: [0 .. TPB*10) = p1 rows, [TPB*10 .. TPB*20) = p2 rows (linear, pitch 10)
    // phase 3: [0 .. TPB*19) = output rows (stride 19) -- reuses the same buffer
    __shared__ float sm[TPB * 20];
    float4* sm4 = (float4*)sm;

    const int tid = threadIdx.x;
    const long long base = (long long)blockIdx.x * TPB;
    const int rows = (B - base < TPB) ? (int)(B - base) : TPB;
    const bool full = (rows == TPB);

    // ---- Phase 1: coalesced vectorized global -> smem ----
    if (full) {
        const float4* g14 = (const float4*)(p1 + base * 10);
        const float4* g24 = (const float4*)(p2 + base * 10);
        #pragma unroll
        for (int i = tid; i < NV4_IN; i += TPB) {
            sm4[i]          = __ldcs(&g14[i]);
            sm4[NV4_IN + i] = __ldcs(&g24[i]);
        }
    } else {
        const float* g1 = p1 + base * 10;
        const float* g2 = p2 + base * 10;
        const int nElems = rows * 10;
        for (int i = tid; i < nElems; i += TPB) {
            sm[i]            = g1[i];
            sm[TPB * 10 + i] = g2[i];
        }
    }
    __syncthreads();

    // ---- Phase 2: per-row convolution + normalize in registers ----
    float r[19];
    if (tid < rows) {
        float a[10], b[10];
        #pragma unroll
        for (int i = 0; i < 10; i++) {
            a[i] = sm[tid * 10 + i];
            b[i] = sm[TPB * 10 + tid * 10 + i];
        }
        #pragma unroll
        for (int k = 0; k < 19; k++) r[k] = 0.0f;
        #pragma unroll
        for (int i = 0; i < 10; i++) {
            #pragma unroll
            for (int j = 0; j < 10; j++) {
                r[i + j] = fmaf(a[i], b[j], r[i + j]);
            }
        }
        float s = 0.0f;
        #pragma unroll
        for (int k = 0; k < 19; k++) s += r[k];
        float inv = 1.0f / (s + 1e-9f);
        #pragma unroll
        for (int k = 0; k < 19; k++) r[k] *= inv;
    }

    __syncthreads();   // input staging consumed; reuse smem for output

    // ---- Phase 3: smem stage (stride 19) -> vectorized coalesced store ----
    if (tid < rows) {
        #pragma unroll
        for (int k = 0; k < 19; k++) sm[tid * 19 + k] = r[k];
    }
    __syncthreads();

    if (full) {
        float4* go4 = (float4*)(out + base * 19);
        #pragma unroll
        for (int i = tid; i < NV4_OUT; i += TPB) {
            __stcs(&go4[i], sm4[i]);
        }
    } else {
        float* go = out + base * 19;
        const int nOut = rows * 19;
        for (int i = tid; i < nOut; i += TPB) go[i] = sm[i];
    }
}

extern "C" void kernel_launch(void* const* d_in, const int* in_sizes, int n_in,
                              void* d_out, int out_size) {
    const float* p1 = (const float*)d_in[0];
    const float* p2 = (const float*)d_in[1];
    float* out = (float*)d_out;
    const int B = in_sizes[0] / 10;
    const int grid = (B + TPB - 1) / TPB;
    dpl_add_kernel<<<grid, TPB>>>(p1, p2, out, B);
}